// round 1
// baseline (speedup 1.0000x reference)
#include <cuda_runtime.h>
#include <cstdint>

// Problem constants
#define NVEC   65536      // 16 * 64 * 64 vectors
#define DIM    256        // embed dim (K)
#define NCODE  2048       // codebook size (N)
#define HW     4096       // 64*64
#define NBATCH 16
#define TOTAL_ELEMS 16777216  // 16*256*64*64

// GEMM tiling
#define MT     128        // M tile per CTA
#define NT     128        // N tile per CTA
#define KT     128        // K staged half for B
#define BS_LD  132        // NT + 4 pad (row stride stays 16B aligned)

#define SMEM_FLOATS (DIM*MT + KT*BS_LD)
#define SMEM_BYTES  (SMEM_FLOATS * 4)

#define GATHER_BLOCKS 16384   // 16384 blocks * 256 thr * 4 elems = 16.7M

__device__ int   g_argmin[NVEC];
__device__ float g_wnorm[NCODE];
__device__ float g_part[GATHER_BLOCKS];

// ---- packed f32x2 helpers (Blackwell FFMA2 path; ptxas only emits via PTX) ----
static __device__ __forceinline__ unsigned long long dup2(float a) {
    unsigned long long r;
    asm("mov.b64 %0, {%1, %1};" : "=l"(r) : "f"(a));
    return r;
}
static __device__ __forceinline__ unsigned long long pk2(float lo, float hi) {
    unsigned long long r;
    asm("mov.b64 %0, {%1, %2};" : "=l"(r) : "f"(lo), "f"(hi));
    return r;
}
static __device__ __forceinline__ void fma2(unsigned long long& d,
                                            unsigned long long a,
                                            unsigned long long b) {
    asm("fma.rn.f32x2 %0, %1, %2, %3;" : "=l"(d) : "l"(a), "l"(b), "l"(d));
}
static __device__ __forceinline__ void unpk2(unsigned long long v, float& lo, float& hi) {
    asm("mov.b64 {%0, %1}, %2;" : "=f"(lo), "=f"(hi) : "l"(v));
}

// ============================================================================
// Kernel 0: codebook row norms  wnorm[j] = sum_c w[j][c]^2
// One warp per codebook row.
// ============================================================================
__global__ void __launch_bounds__(256) wnorm_kernel(const float* __restrict__ w) {
    int gwarp = (blockIdx.x * blockDim.x + threadIdx.x) >> 5;
    int lane  = threadIdx.x & 31;
    if (gwarp >= NCODE) return;
    const float4* row = reinterpret_cast<const float4*>(w + (size_t)gwarp * DIM);
    float4 v0 = row[lane];
    float4 v1 = row[lane + 32];
    float s = v0.x*v0.x + v0.y*v0.y + v0.z*v0.z + v0.w*v0.w
            + v1.x*v1.x + v1.y*v1.y + v1.z*v1.z + v1.w*v1.w;
    #pragma unroll
    for (int o = 16; o > 0; o >>= 1)
        s += __shfl_xor_sync(0xFFFFFFFF, s, o);
    if (lane == 0) g_wnorm[gwarp] = s;
}

// ============================================================================
// Kernel 1: fused distance GEMM + argmin.
// CTA: 128 vectors (rows) x all 2048 codes, K=256.
// A (x slice) resident in smem k-major [256][128].
// B (codes) staged transposed in K-halves [128k][128n (+pad)].
// Thread 8x8 tile: 8 rows (dup-packed) x 4 f32x2 column pairs.
// dist = ||w||^2 - 2*dot  (the ||x||^2 term is argmin-invariant).
// ============================================================================
__global__ void __launch_bounds__(256, 1)
dist_argmin_kernel(const float* __restrict__ x, const float* __restrict__ w) {
    extern __shared__ float smem_f[];
    float* As = smem_f;             // [DIM][MT]  k-major
    float* Bs = smem_f + DIM * MT;  // [KT][BS_LD]

    const int t  = threadIdx.x;
    const int tx = t & 15;          // column group
    const int ty = t >> 4;          // row group

    const int m0  = blockIdx.x * MT;     // global vector base (same batch image)
    const int b   = m0 >> 12;            // m0 / 4096
    const int hw0 = m0 & (HW - 1);
    const float* xb = x + (size_t)b * (DIM * HW) + hw0;

    // Load A tile: As[c][m] = x[b][c][hw0+m]   (coalesced gmem, conflict-free sts)
    #pragma unroll
    for (int it = t; it < DIM * MT; it += 256) {
        int c = it >> 7;
        int m = it & (MT - 1);
        As[c * MT + m] = xb[(size_t)c * HW + m];
    }

    float minv[8];
    int   mini[8];
    #pragma unroll
    for (int r = 0; r < 8; ++r) { minv[r] = 3.4e38f; mini[r] = 0; }

    __syncthreads();

    for (int nt = 0; nt < NCODE / NT; ++nt) {
        const int n0 = nt * NT;

        unsigned long long acc[8][4];
        #pragma unroll
        for (int r = 0; r < 8; ++r)
            #pragma unroll
            for (int c = 0; c < 4; ++c)
                acc[r][c] = 0ull;  // packed {+0.f, +0.f}

        #pragma unroll
        for (int kh = 0; kh < 2; ++kh) {
            const int k0 = kh * KT;
            __syncthreads();  // previous Bs consumers done
            // Load+transpose B half: Bs[cc][j] = w[n0+j][k0+cc]
            // warp lanes take consecutive j -> conflict-free smem stores;
            // gmem reads are 16B-per-lane strided (L2-resident codebook).
            #pragma unroll
            for (int it = t; it < (NT * KT) / 4; it += 256) {
                int j  = it & (NT - 1);       // code within tile (fast within warp)
                int cq = it >> 7;             // float4 index along K
                float4 v = *reinterpret_cast<const float4*>(
                    w + (size_t)(n0 + j) * DIM + k0 + cq * 4);
                Bs[(cq * 4 + 0) * BS_LD + j] = v.x;
                Bs[(cq * 4 + 1) * BS_LD + j] = v.y;
                Bs[(cq * 4 + 2) * BS_LD + j] = v.z;
                Bs[(cq * 4 + 3) * BS_LD + j] = v.w;
            }
            __syncthreads();

            #pragma unroll 8
            for (int k = 0; k < KT; ++k) {
                const float* ar_p = &As[(k0 + k) * MT + ty * 8];
                float4 a0 = *reinterpret_cast<const float4*>(ar_p);
                float4 a1 = *reinterpret_cast<const float4*>(ar_p + 4);
                const float* bp_p = &Bs[k * BS_LD + tx * 8];
                float4 b0 = *reinterpret_cast<const float4*>(bp_p);
                float4 b1 = *reinterpret_cast<const float4*>(bp_p + 4);

                unsigned long long bp[4];
                bp[0] = pk2(b0.x, b0.y);
                bp[1] = pk2(b0.z, b0.w);
                bp[2] = pk2(b1.x, b1.y);
                bp[3] = pk2(b1.z, b1.w);

                unsigned long long ar[8];
                ar[0] = dup2(a0.x); ar[1] = dup2(a0.y);
                ar[2] = dup2(a0.z); ar[3] = dup2(a0.w);
                ar[4] = dup2(a1.x); ar[5] = dup2(a1.y);
                ar[6] = dup2(a1.z); ar[7] = dup2(a1.w);

                #pragma unroll
                for (int r = 0; r < 8; ++r) {
                    fma2(acc[r][0], ar[r], bp[0]);
                    fma2(acc[r][1], ar[r], bp[1]);
                    fma2(acc[r][2], ar[r], bp[2]);
                    fma2(acc[r][3], ar[r], bp[3]);
                }
            }
        }

        // Epilogue: dist = wnorm - 2*dot, running argmin (ascending n order;
        // strict < keeps the lowest index on exact ties, matching jnp.argmin)
        const int nbase = n0 + tx * 8;
        #pragma unroll
        for (int r = 0; r < 8; ++r) {
            #pragma unroll
            for (int c2 = 0; c2 < 4; ++c2) {
                float lo, hi;
                unpk2(acc[r][c2], lo, hi);
                int n = nbase + c2 * 2;
                float d0 = fmaf(-2.0f, lo, g_wnorm[n]);
                float d1 = fmaf(-2.0f, hi, g_wnorm[n + 1]);
                if (d0 < minv[r]) { minv[r] = d0; mini[r] = n; }
                if (d1 < minv[r]) { minv[r] = d1; mini[r] = n + 1; }
            }
        }
    }

    // Cross-thread reduction: 16 tx candidates per row -> argmin per row.
    __syncthreads();  // done with As/Bs; reuse smem
    float* sval = smem_f;                                  // [MT][16]
    int*   sidx = reinterpret_cast<int*>(smem_f + MT * 16); // [MT][16]
    #pragma unroll
    for (int r = 0; r < 8; ++r) {
        int row = ty * 8 + r;
        sval[row * 16 + tx] = minv[r];
        sidx[row * 16 + tx] = mini[r];
    }
    __syncthreads();
    if (t < MT) {
        float bv = sval[t * 16];
        int   bi = sidx[t * 16];
        #pragma unroll
        for (int j = 1; j < 16; ++j) {
            float v = sval[t * 16 + j];
            int   i = sidx[t * 16 + j];
            if (v < bv || (v == bv && i < bi)) { bv = v; bi = i; }
        }
        g_argmin[m0 + t] = bi;
    }
}

// ============================================================================
// Kernel 2: gather quantized output + per-block loss partial sums.
// out[b][c][hw] = w[argmin[b*4096+hw]][c]; partial += (q - x)^2
// Deterministic: fixed-order block tree reduction, no float atomics.
// ============================================================================
__global__ void __launch_bounds__(256)
gather_loss_kernel(const float* __restrict__ x, const float* __restrict__ w,
                   float* __restrict__ out) {
    __shared__ float red[256];
    const int t = threadIdx.x;
    const long base = ((long)blockIdx.x * 256 + t) * 4;

    float4 xv = *reinterpret_cast<const float4*>(x + base);
    int hw = (int)(base & (HW - 1));
    int c  = (int)((base >> 12) & (DIM - 1));
    int b  = (int)(base >> 20);
    int m  = (b << 12) | hw;

    int4 jj = *reinterpret_cast<const int4*>(g_argmin + m);
    float4 q;
    q.x = w[(size_t)jj.x * DIM + c];
    q.y = w[(size_t)jj.y * DIM + c];
    q.z = w[(size_t)jj.z * DIM + c];
    q.w = w[(size_t)jj.w * DIM + c];
    *reinterpret_cast<float4*>(out + base) = q;

    float d0 = q.x - xv.x, d1 = q.y - xv.y, d2 = q.z - xv.z, d3 = q.w - xv.w;
    red[t] = d0 * d0 + d1 * d1 + d2 * d2 + d3 * d3;
    __syncthreads();
    #pragma unroll
    for (int o = 128; o > 0; o >>= 1) {
        if (t < o) red[t] += red[t + o];
        __syncthreads();
    }
    if (t == 0) g_part[blockIdx.x] = red[0];
}

// ============================================================================
// Kernel 3: deterministic final loss reduction.
// ============================================================================
__global__ void __launch_bounds__(256)
finalize_kernel(float* __restrict__ out, int loss_idx) {
    __shared__ float red[256];
    const int t = threadIdx.x;
    float s = 0.0f;
    #pragma unroll
    for (int i = 0; i < GATHER_BLOCKS / 256; ++i)
        s += g_part[t + (i << 8)];
    red[t] = s;
    __syncthreads();
    #pragma unroll
    for (int o = 128; o > 0; o >>= 1) {
        if (t < o) red[t] += red[t + o];
        __syncthreads();
    }
    if (t == 0)
        out[loss_idx] = 0.25f * red[0] / (float)TOTAL_ELEMS;
}

// ============================================================================
extern "C" void kernel_launch(void* const* d_in, const int* in_sizes, int n_in,
                              void* d_out, int out_size) {
    const float* x = (const float*)d_in[0];   // [16,256,64,64]
    const float* w = (const float*)d_in[1];   // [2048,256]
    float* out = (float*)d_out;               // 16777216 quantized + 1 loss

    cudaFuncSetAttribute(dist_argmin_kernel,
                         cudaFuncAttributeMaxDynamicSharedMemorySize, SMEM_BYTES);

    wnorm_kernel<<<NCODE * 32 / 256, 256>>>(w);
    dist_argmin_kernel<<<NVEC / MT, 256, SMEM_BYTES>>>(x, w);
    gather_loss_kernel<<<GATHER_BLOCKS, 256>>>(x, w, out);
    finalize_kernel<<<1, 256>>>(out, out_size - 1);
}

// round 3
// speedup vs baseline: 3.3674x; 3.3674x over previous
#include <cuda_runtime.h>
#include <cuda_fp16.h>
#include <cstdint>

// ---------------- problem constants ----------------
#define NVEC   65536
#define DIM    256
#define NCODE  2048
#define HW     4096
#define TOTAL_ELEMS 16777216
#define GATHER_BLOCKS 16384
#define MARGIN 0.25f

// ---------------- GEMM config ----------------
#define MT 128          // M rows per CTA
#define NTILE 128       // N per tile
#define NTILES 16       // 2048 / 128
#define KSTEPS 16       // 256 / 16

// smem layout (bytes, dynamic)
#define SM_A   0
#define SM_B0  65536
#define SM_B1  131072
#define SM_WN  196608
#define SM_TOT 204800

// ---------------- device globals ----------------
__device__ int    g_argmin[NVEC];
__device__ float  g_wnorm[NCODE];
__device__ float  g_part[GATHER_BLOCKS];
__device__ __half g_xh[(size_t)NVEC * DIM];
__device__ __half g_wh[(size_t)NCODE * DIM];
__device__ int    g_qcount;
__device__ int    g_qm[NVEC], g_qa[NVEC], g_qb[NVEC], g_qc[NVEC];

// ---------------- PTX helpers ----------------
static __device__ __forceinline__ uint32_t smem_u32(const void* p) {
    uint32_t a;
    asm("{ .reg .u64 t; cvta.to.shared.u64 t, %1; cvt.u32.u64 %0, t; }" : "=r"(a) : "l"(p));
    return a;
}
#define CP_ASYNC16(dst, src) \
    asm volatile("cp.async.cg.shared.global [%0], [%1], 16;" :: "r"(dst), "l"(src))
#define CP_COMMIT() asm volatile("cp.async.commit_group;" ::: "memory")
#define CP_WAIT(n)  asm volatile("cp.async.wait_group %0;" :: "n"(n) : "memory")

static __device__ __forceinline__ void ldsm4(uint32_t* r, uint32_t addr) {
    asm volatile("ldmatrix.sync.aligned.m8n8.x4.shared.b16 {%0,%1,%2,%3}, [%4];"
        : "=r"(r[0]), "=r"(r[1]), "=r"(r[2]), "=r"(r[3]) : "r"(addr));
}
static __device__ __forceinline__ void mma16816(float* c, const uint32_t* a,
                                                uint32_t b0, uint32_t b1) {
    asm volatile("mma.sync.aligned.m16n8k16.row.col.f32.f16.f16.f32 "
        "{%0,%1,%2,%3}, {%4,%5,%6,%7}, {%8,%9}, {%0,%1,%2,%3};"
        : "+f"(c[0]), "+f"(c[1]), "+f"(c[2]), "+f"(c[3])
        : "r"(a[0]), "r"(a[1]), "r"(a[2]), "r"(a[3]), "r"(b0), "r"(b1));
}

// swizzled byte offset for (row, 16B-chunk) in a 512B-per-row tile
static __device__ __forceinline__ uint32_t sw_off(int row, int c16) {
    return (uint32_t)row * 512u + ((uint32_t)(c16 ^ (row & 7)) << 4);
}

static __device__ __forceinline__ bool better(float a, int ia, float b, int ib) {
    return (a < b) || (a == b && ia < ib);
}
static __device__ __forceinline__ void ins3(float d, int n, float* v, int* ix) {
    if (d < v[0])      { v[2]=v[1]; ix[2]=ix[1]; v[1]=v[0]; ix[1]=ix[0]; v[0]=d; ix[0]=n; }
    else if (d < v[1]) { v[2]=v[1]; ix[2]=ix[1]; v[1]=d; ix[1]=n; }
    else if (d < v[2]) { v[2]=d; ix[2]=n; }
}
static __device__ __forceinline__ void ins3t(float d, int n, float* v, int* ix) {
    if (better(d, n, v[0], ix[0]))      { v[2]=v[1]; ix[2]=ix[1]; v[1]=v[0]; ix[1]=ix[0]; v[0]=d; ix[0]=n; }
    else if (better(d, n, v[1], ix[1])) { v[2]=v[1]; ix[2]=ix[1]; v[1]=d; ix[1]=n; }
    else if (better(d, n, v[2], ix[2])) { v[2]=d; ix[2]=n; }
}

// ============================================================================
// Kernel 0: codebook norms (exact fp32) + queue-counter reset
// ============================================================================
__global__ void __launch_bounds__(256) wnorm_kernel(const float* __restrict__ w) {
    if (blockIdx.x == 0 && threadIdx.x == 0) g_qcount = 0;
    int gwarp = (blockIdx.x * blockDim.x + threadIdx.x) >> 5;
    int lane  = threadIdx.x & 31;
    if (gwarp >= NCODE) return;
    const float4* row = reinterpret_cast<const float4*>(w + (size_t)gwarp * DIM);
    float4 v0 = row[lane];
    float4 v1 = row[lane + 32];
    float s = v0.x*v0.x + v0.y*v0.y + v0.z*v0.z + v0.w*v0.w
            + v1.x*v1.x + v1.y*v1.y + v1.z*v1.z + v1.w*v1.w;
    #pragma unroll
    for (int o = 16; o > 0; o >>= 1)
        s += __shfl_xor_sync(0xFFFFFFFF, s, o);
    if (lane == 0) g_wnorm[gwarp] = s;
}

// ============================================================================
// Kernel 1: codebook -> fp16
// ============================================================================
__global__ void __launch_bounds__(256) wsplit_kernel(const float* __restrict__ w) {
    int i = blockIdx.x * 256 + threadIdx.x;   // grid covers NCODE*DIM
    g_wh[i] = __float2half_rn(w[i]);
}

// ============================================================================
// Kernel 2: x transpose [b][c][hw] -> g_xh[m][c] fp16 (32x32 smem tiles)
// ============================================================================
__global__ void __launch_bounds__(256) xsplit_kernel(const float* __restrict__ x) {
    __shared__ float t[32][33];
    int bx = blockIdx.x, by = blockIdx.y, b = blockIdx.z;
    int tx = threadIdx.x & 31, ty = threadIdx.x >> 5;
    const float* xp = x + (size_t)b * (DIM * HW) + (size_t)(by * 32) * HW + bx * 32;
    #pragma unroll
    for (int i = 0; i < 4; ++i)
        t[ty + i * 8][tx] = xp[(size_t)(ty + i * 8) * HW + tx];
    __syncthreads();
    #pragma unroll
    for (int i = 0; i < 4; ++i) {
        int hwr = ty + i * 8;
        int m = b * HW + bx * 32 + hwr;
        g_xh[(size_t)m * DIM + by * 32 + tx] = __float2half_rn(t[tx][hwr]);
    }
}

// ============================================================================
// Kernel 3: fp16 HMMA distance GEMM + fused top-3 argmin.
// dist = ||w||^2 - 2*(x.w)   (||x||^2 is argmin-invariant)
// ============================================================================
static __device__ __forceinline__ void load_b_tile(uint32_t dstbase, int n0, int tid) {
    const __half* bsrc = g_wh + (size_t)n0 * DIM;
    #pragma unroll
    for (int it = 0; it < 16; ++it) {
        int id = tid + it * 256;
        int row = id >> 5, c16 = id & 31;
        CP_ASYNC16(dstbase + sw_off(row, c16), bsrc + (size_t)row * DIM + c16 * 8);
    }
    CP_COMMIT();
}

__global__ void __launch_bounds__(256, 1) mma_argmin_kernel() {
    extern __shared__ char smem[];
    const uint32_t sb = smem_u32(smem);
    const uint32_t sA = sb + SM_A;
    const uint32_t sB[2] = { sb + SM_B0, sb + SM_B1 };
    float* wns = reinterpret_cast<float*>(smem + SM_WN);

    const int tid = threadIdx.x;
    const int lane = tid & 31, wid = tid >> 5;
    const int warp_m = wid & 3;      // 4 m-quadrants of 32 rows
    const int warp_n = wid >> 2;     // 2 n-halves of 64 cols
    const int m0 = blockIdx.x * MT;

    // wnorm -> smem
    #pragma unroll
    for (int i = tid; i < NCODE; i += 256) wns[i] = g_wnorm[i];

    // A tile (128 x 256 fp16 = 64KB) via cp.async
    {
        const __half* asrc = g_xh + (size_t)m0 * DIM;
        #pragma unroll
        for (int it = 0; it < 16; ++it) {
            int id = tid + it * 256;
            int row = id >> 5, c16 = id & 31;
            CP_ASYNC16(sA + sw_off(row, c16), asrc + (size_t)row * DIM + c16 * 8);
        }
        CP_COMMIT();
    }
    load_b_tile(sB[0], 0, tid);
    load_b_tile(sB[1], NTILE, tid);
    CP_WAIT(1);              // A + B0 ready
    __syncthreads();

    // per-thread top-3 for 4 row-slots: slot = mf*2 + half
    float v[4][3]; int ix[4][3];
    #pragma unroll
    for (int s = 0; s < 4; ++s)
        #pragma unroll
        for (int k = 0; k < 3; ++k) { v[s][k] = 3.4e38f; ix[s][k] = 0; }

    #pragma unroll 1
    for (int nt = 0; nt < NTILES; ++nt) {
        const uint32_t bB = sB[nt & 1];
        float acc[2][8][4];
        #pragma unroll
        for (int mf = 0; mf < 2; ++mf)
            #pragma unroll
            for (int nf = 0; nf < 8; ++nf)
                #pragma unroll
                for (int c = 0; c < 4; ++c) acc[mf][nf][c] = 0.f;

        #pragma unroll
        for (int ks = 0; ks < KSTEPS; ++ks) {
            uint32_t a_regs[2][4];
            #pragma unroll
            for (int mf = 0; mf < 2; ++mf) {
                int row = warp_m * 32 + mf * 16 + (lane & 15);
                int c16 = ks * 2 + (lane >> 4);
                ldsm4(a_regs[mf], sA + sw_off(row, c16));
            }
            #pragma unroll
            for (int ng = 0; ng < 4; ++ng) {
                uint32_t b_regs[4];
                int row = warp_n * 64 + ng * 16 + (lane & 7) + ((lane >> 4) << 3);
                int c16 = ks * 2 + ((lane >> 3) & 1);
                ldsm4(b_regs, bB + sw_off(row, c16));
                #pragma unroll
                for (int mf = 0; mf < 2; ++mf) {
                    mma16816(acc[mf][ng * 2],     a_regs[mf], b_regs[0], b_regs[1]);
                    mma16816(acc[mf][ng * 2 + 1], a_regs[mf], b_regs[2], b_regs[3]);
                }
            }
        }

        // epilogue: dist + top-3 update (ascending n order)
        #pragma unroll
        for (int nf = 0; nf < 8; ++nf) {
            int n = nt * NTILE + warp_n * 64 + nf * 8 + 2 * (lane & 3);
            float wn0 = wns[n], wn1 = wns[n + 1];
            #pragma unroll
            for (int mf = 0; mf < 2; ++mf) {
                float d0 = fmaf(-2.f, acc[mf][nf][0], wn0);
                float d1 = fmaf(-2.f, acc[mf][nf][1], wn1);
                float d2 = fmaf(-2.f, acc[mf][nf][2], wn0);
                float d3 = fmaf(-2.f, acc[mf][nf][3], wn1);
                ins3(d0, n,     v[mf*2],   ix[mf*2]);
                ins3(d1, n + 1, v[mf*2],   ix[mf*2]);
                ins3(d2, n,     v[mf*2+1], ix[mf*2+1]);
                ins3(d3, n + 1, v[mf*2+1], ix[mf*2+1]);
            }
        }

        __syncthreads();                 // all warps done with Bs[nt&1]
        if (nt + 2 < NTILES) {
            load_b_tile(sB[nt & 1], (nt + 2) * NTILE, tid);
            CP_WAIT(1);                  // tile nt+1 complete
        } else {
            CP_WAIT(0);
        }
        __syncthreads();
    }

    // cross-thread reduction: 8 slots per row (warp_n x (lane&3)), top-3 merge
    __syncthreads();
    float4* red = reinterpret_cast<float4*>(smem);   // reuse A region: 128*8*32B
    #pragma unroll
    for (int s = 0; s < 4; ++s) {
        int mf = s >> 1, half = s & 1;
        int row = warp_m * 32 + mf * 16 + half * 8 + (lane >> 2);
        int slot = warp_n * 4 + (lane & 3);
        red[(row * 8 + slot) * 2]     = make_float4(v[s][0], __int_as_float(ix[s][0]),
                                                    v[s][1], __int_as_float(ix[s][1]));
        red[(row * 8 + slot) * 2 + 1] = make_float4(v[s][2], __int_as_float(ix[s][2]), 0.f, 0.f);
    }
    __syncthreads();
    if (tid < MT) {
        float bv[3] = {3.4e38f, 3.4e38f, 3.4e38f};
        int   bi[3] = {0, 0, 0};
        #pragma unroll
        for (int s = 0; s < 8; ++s) {
            float4 e0 = red[(tid * 8 + s) * 2];
            float4 e1 = red[(tid * 8 + s) * 2 + 1];
            ins3t(e0.x, __float_as_int(e0.y), bv, bi);
            ins3t(e0.z, __float_as_int(e0.w), bv, bi);
            ins3t(e1.x, __float_as_int(e1.y), bv, bi);
        }
        int m = m0 + tid;
        g_argmin[m] = bi[0];
        if (bv[1] - bv[0] < MARGIN) {
            int p = atomicAdd(&g_qcount, 1);
            g_qm[p] = m; g_qa[p] = bi[0]; g_qb[p] = bi[1]; g_qc[p] = bi[2];
        }
    }
}

// ============================================================================
// Kernel 4: exact fp32 rescue among top-3 candidates (tiny queue).
// ============================================================================
__global__ void __launch_bounds__(256)
rescue_kernel(const float* __restrict__ x, const float* __restrict__ w) {
    const int gw = (blockIdx.x * blockDim.x + threadIdx.x) >> 5;
    const int lane = threadIdx.x & 31;
    const int nw = (gridDim.x * blockDim.x) >> 5;
    const int cnt = g_qcount;
    for (int i = gw; i < cnt; i += nw) {
        int m = g_qm[i], ja = g_qa[i], jb = g_qb[i], jc = g_qc[i];
        int b = m >> 12, hw = m & (HW - 1);
        const float* xp = x + (size_t)b * (DIM * HW) + hw;
        float sa = 0.f, sb2 = 0.f, sc = 0.f;
        #pragma unroll 4
        for (int c = lane; c < DIM; c += 32) {
            float xv = xp[(size_t)c * HW];
            sa  = fmaf(xv, w[(size_t)ja * DIM + c], sa);
            sb2 = fmaf(xv, w[(size_t)jb * DIM + c], sb2);
            sc  = fmaf(xv, w[(size_t)jc * DIM + c], sc);
        }
        #pragma unroll
        for (int o = 16; o > 0; o >>= 1) {
            sa  += __shfl_xor_sync(0xFFFFFFFF, sa, o);
            sb2 += __shfl_xor_sync(0xFFFFFFFF, sb2, o);
            sc  += __shfl_xor_sync(0xFFFFFFFF, sc, o);
        }
        if (lane == 0) {
            float da = fmaf(-2.0f, sa,  g_wnorm[ja]);
            float db = fmaf(-2.0f, sb2, g_wnorm[jb]);
            float dc = fmaf(-2.0f, sc,  g_wnorm[jc]);
            float wv = da; int wi = ja;
            if (better(db, jb, wv, wi)) { wv = db; wi = jb; }
            if (better(dc, jc, wv, wi)) { wv = dc; wi = jc; }
            g_argmin[m] = wi;
        }
    }
}

// ============================================================================
// Kernel 5: gather quantized output + per-block loss partials.
// ============================================================================
__global__ void __launch_bounds__(256)
gather_loss_kernel(const float* __restrict__ x, const float* __restrict__ w,
                   float* __restrict__ out) {
    __shared__ float red[256];
    const int t = threadIdx.x;
    const long base = ((long)blockIdx.x * 256 + t) * 4;

    float4 xv = *reinterpret_cast<const float4*>(x + base);
    int hw = (int)(base & (HW - 1));
    int c  = (int)((base >> 12) & (DIM - 1));
    int b  = (int)(base >> 20);
    int m  = (b << 12) | hw;

    int4 jj = *reinterpret_cast<const int4*>(g_argmin + m);
    float4 q;
    q.x = w[(size_t)jj.x * DIM + c];
    q.y = w[(size_t)jj.y * DIM + c];
    q.z = w[(size_t)jj.z * DIM + c];
    q.w = w[(size_t)jj.w * DIM + c];
    *reinterpret_cast<float4*>(out + base) = q;

    float d0 = q.x - xv.x, d1 = q.y - xv.y, d2 = q.z - xv.z, d3 = q.w - xv.w;
    red[t] = d0 * d0 + d1 * d1 + d2 * d2 + d3 * d3;
    __syncthreads();
    #pragma unroll
    for (int o = 128; o > 0; o >>= 1) {
        if (t < o) red[t] += red[t + o];
        __syncthreads();
    }
    if (t == 0) g_part[blockIdx.x] = red[0];
}

__global__ void __launch_bounds__(256)
finalize_kernel(float* __restrict__ out, int loss_idx) {
    __shared__ float red[256];
    const int t = threadIdx.x;
    float s = 0.0f;
    #pragma unroll
    for (int i = 0; i < GATHER_BLOCKS / 256; ++i)
        s += g_part[t + (i << 8)];
    red[t] = s;
    __syncthreads();
    #pragma unroll
    for (int o = 128; o > 0; o >>= 1) {
        if (t < o) red[t] += red[t + o];
        __syncthreads();
    }
    if (t == 0)
        out[loss_idx] = 0.25f * red[0] / (float)TOTAL_ELEMS;
}

// ============================================================================
extern "C" void kernel_launch(void* const* d_in, const int* in_sizes, int n_in,
                              void* d_out, int out_size) {
    const float* x = (const float*)d_in[0];   // [16,256,64,64]
    const float* w = (const float*)d_in[1];   // [2048,256]
    float* out = (float*)d_out;

    cudaFuncSetAttribute(mma_argmin_kernel,
                         cudaFuncAttributeMaxDynamicSharedMemorySize, SM_TOT);

    wnorm_kernel<<<NCODE * 32 / 256, 256>>>(w);
    wsplit_kernel<<<NCODE * DIM / 256, 256>>>(w);
    xsplit_kernel<<<dim3(HW / 32, DIM / 32, 16), 256>>>(x);
    mma_argmin_kernel<<<NVEC / MT, 256, SM_TOT>>>();
    rescue_kernel<<<64, 256>>>(x, w);
    gather_loss_kernel<<<GATHER_BLOCKS, 256>>>(x, w, out);
    finalize_kernel<<<1, 256>>>(out, out_size - 1);
}

// round 4
// speedup vs baseline: 4.4510x; 1.3218x over previous
#include <cuda_runtime.h>
#include <cuda_fp16.h>
#include <cstdint>

// ---------------- problem constants ----------------
#define NVEC   65536
#define DIM    256
#define NCODE  2048
#define HW     4096
#define TOTAL_ELEMS 16777216
#define GATHER_BLOCKS 16384
#define MARGIN 0.25f

// ---------------- GEMM config ----------------
#define MT 128          // M rows per CTA
#define NTILE 128       // N per tile
#define NTILES 16       // 2048 / 128
#define KSTEPS 16       // 256 / 16
#define NTHR 512        // 16 warps

// smem layout (bytes, dynamic)
#define SM_A   0
#define SM_B0  65536
#define SM_B1  131072
#define SM_WN  196608
#define SM_TOT 204800

// ---------------- device globals ----------------
__device__ int    g_argmin[NVEC];
__device__ float  g_wnorm[NCODE];
__device__ float  g_part[GATHER_BLOCKS];
__device__ __half g_xh[(size_t)NVEC * DIM];
__device__ __half g_wh[(size_t)NCODE * DIM];
__device__ int    g_qcount;
__device__ int    g_qm[NVEC], g_qa[NVEC], g_qb[NVEC], g_qc[NVEC];

// ---------------- PTX helpers ----------------
static __device__ __forceinline__ uint32_t smem_u32(const void* p) {
    uint32_t a;
    asm("{ .reg .u64 t; cvta.to.shared.u64 t, %1; cvt.u32.u64 %0, t; }" : "=r"(a) : "l"(p));
    return a;
}
#define CP_ASYNC16(dst, src) \
    asm volatile("cp.async.cg.shared.global [%0], [%1], 16;" :: "r"(dst), "l"(src))
#define CP_COMMIT() asm volatile("cp.async.commit_group;" ::: "memory")
#define CP_WAIT(n)  asm volatile("cp.async.wait_group %0;" :: "n"(n) : "memory")

static __device__ __forceinline__ void ldsm4(uint32_t* r, uint32_t addr) {
    asm volatile("ldmatrix.sync.aligned.m8n8.x4.shared.b16 {%0,%1,%2,%3}, [%4];"
        : "=r"(r[0]), "=r"(r[1]), "=r"(r[2]), "=r"(r[3]) : "r"(addr));
}
static __device__ __forceinline__ void mma16816(float* c, const uint32_t* a,
                                                uint32_t b0, uint32_t b1) {
    asm volatile("mma.sync.aligned.m16n8k16.row.col.f32.f16.f16.f32 "
        "{%0,%1,%2,%3}, {%4,%5,%6,%7}, {%8,%9}, {%0,%1,%2,%3};"
        : "+f"(c[0]), "+f"(c[1]), "+f"(c[2]), "+f"(c[3])
        : "r"(a[0]), "r"(a[1]), "r"(a[2]), "r"(a[3]), "r"(b0), "r"(b1));
}

// swizzled byte offset for (row, 16B-chunk) in a 512B-per-row tile
static __device__ __forceinline__ uint32_t sw_off(int row, int c16) {
    return (uint32_t)row * 512u + ((uint32_t)(c16 ^ (row & 7)) << 4);
}

static __device__ __forceinline__ bool better(float a, int ia, float b, int ib) {
    return (a < b) || (a == b && ia < ib);
}
static __device__ __forceinline__ void ins2(float d, int n, float* v, int* ix) {
    if (d < v[0])      { v[1]=v[0]; ix[1]=ix[0]; v[0]=d; ix[0]=n; }
    else if (d < v[1]) { v[1]=d; ix[1]=n; }
}
static __device__ __forceinline__ void ins3t(float d, int n, float* v, int* ix) {
    if (better(d, n, v[0], ix[0]))      { v[2]=v[1]; ix[2]=ix[1]; v[1]=v[0]; ix[1]=ix[0]; v[0]=d; ix[0]=n; }
    else if (better(d, n, v[1], ix[1])) { v[2]=v[1]; ix[2]=ix[1]; v[1]=d; ix[1]=n; }
    else if (better(d, n, v[2], ix[2])) { v[2]=d; ix[2]=n; }
}

// ============================================================================
// Kernel 0: codebook norms (exact fp32) + queue-counter reset
// ============================================================================
__global__ void __launch_bounds__(256) wnorm_kernel(const float* __restrict__ w) {
    if (blockIdx.x == 0 && threadIdx.x == 0) g_qcount = 0;
    int gwarp = (blockIdx.x * blockDim.x + threadIdx.x) >> 5;
    int lane  = threadIdx.x & 31;
    if (gwarp >= NCODE) return;
    const float4* row = reinterpret_cast<const float4*>(w + (size_t)gwarp * DIM);
    float4 v0 = row[lane];
    float4 v1 = row[lane + 32];
    float s = v0.x*v0.x + v0.y*v0.y + v0.z*v0.z + v0.w*v0.w
            + v1.x*v1.x + v1.y*v1.y + v1.z*v1.z + v1.w*v1.w;
    #pragma unroll
    for (int o = 16; o > 0; o >>= 1)
        s += __shfl_xor_sync(0xFFFFFFFF, s, o);
    if (lane == 0) g_wnorm[gwarp] = s;
}

// ============================================================================
// Kernel 1: codebook -> fp16
// ============================================================================
__global__ void __launch_bounds__(256) wsplit_kernel(const float* __restrict__ w) {
    int i = blockIdx.x * 256 + threadIdx.x;
    g_wh[i] = __float2half_rn(w[i]);
}

// ============================================================================
// Kernel 2: x transpose [b][c][hw] -> g_xh[m][c] fp16 (32x32 smem tiles)
// ============================================================================
__global__ void __launch_bounds__(256) xsplit_kernel(const float* __restrict__ x) {
    __shared__ float t[32][33];
    int bx = blockIdx.x, by = blockIdx.y, b = blockIdx.z;
    int tx = threadIdx.x & 31, ty = threadIdx.x >> 5;
    const float* xp = x + (size_t)b * (DIM * HW) + (size_t)(by * 32) * HW + bx * 32;
    #pragma unroll
    for (int i = 0; i < 4; ++i)
        t[ty + i * 8][tx] = xp[(size_t)(ty + i * 8) * HW + tx];
    __syncthreads();
    #pragma unroll
    for (int i = 0; i < 4; ++i) {
        int hwr = ty + i * 8;
        int m = b * HW + bx * 32 + hwr;
        g_xh[(size_t)m * DIM + by * 32 + tx] = __float2half_rn(t[tx][hwr]);
    }
}

// ============================================================================
// Kernel 3: fp16 HMMA distance GEMM + fused top-k argmin.
// 512 threads, 16 warps: warp grid 4m x 4n, warp tile 32 rows x 32 cols.
// dist = ||w||^2 - 2*(x.w)   (||x||^2 is argmin-invariant)
// ============================================================================
static __device__ __forceinline__ void load_b_tile(uint32_t dstbase, int n0, int tid) {
    const __half* bsrc = g_wh + (size_t)n0 * DIM;
    #pragma unroll
    for (int it = 0; it < 8; ++it) {
        int id = tid + it * NTHR;
        int row = id >> 5, c16 = id & 31;
        CP_ASYNC16(dstbase + sw_off(row, c16), bsrc + (size_t)row * DIM + c16 * 8);
    }
    CP_COMMIT();
}

__global__ void __launch_bounds__(NTHR, 1) mma_argmin_kernel() {
    extern __shared__ char smem[];
    const uint32_t sb = smem_u32(smem);
    const uint32_t sA = sb + SM_A;
    const uint32_t sB[2] = { sb + SM_B0, sb + SM_B1 };
    float* wns = reinterpret_cast<float*>(smem + SM_WN);

    const int tid = threadIdx.x;
    const int lane = tid & 31, wid = tid >> 5;
    const int warp_m = wid & 3;      // 4 m-quadrants of 32 rows
    const int warp_n = wid >> 2;     // 4 n-quarters of 32 cols
    const int m0 = blockIdx.x * MT;

    // wnorm -> smem
    #pragma unroll
    for (int i = tid; i < NCODE; i += NTHR) wns[i] = g_wnorm[i];

    // A tile (128 x 256 fp16 = 64KB) via cp.async
    {
        const __half* asrc = g_xh + (size_t)m0 * DIM;
        #pragma unroll
        for (int it = 0; it < 8; ++it) {
            int id = tid + it * NTHR;
            int row = id >> 5, c16 = id & 31;
            CP_ASYNC16(sA + sw_off(row, c16), asrc + (size_t)row * DIM + c16 * 8);
        }
        CP_COMMIT();
    }
    load_b_tile(sB[0], 0, tid);
    load_b_tile(sB[1], NTILE, tid);
    CP_WAIT(1);              // A + B0 ready
    __syncthreads();

    // per-thread top-2 for 4 row-slots (slot = mf*2 + half)
    float v[4][2]; int ix[4][2];
    #pragma unroll
    for (int s = 0; s < 4; ++s)
        #pragma unroll
        for (int k = 0; k < 2; ++k) { v[s][k] = 3.4e38f; ix[s][k] = 0; }

    #pragma unroll 1
    for (int nt = 0; nt < NTILES; ++nt) {
        const uint32_t bB = sB[nt & 1];
        float acc[2][4][4];
        #pragma unroll
        for (int mf = 0; mf < 2; ++mf)
            #pragma unroll
            for (int nf = 0; nf < 4; ++nf)
                #pragma unroll
                for (int c = 0; c < 4; ++c) acc[mf][nf][c] = 0.f;

        #pragma unroll
        for (int ks = 0; ks < KSTEPS; ++ks) {
            uint32_t a_regs[2][4];
            #pragma unroll
            for (int mf = 0; mf < 2; ++mf) {
                int row = warp_m * 32 + mf * 16 + (lane & 15);
                int c16 = ks * 2 + (lane >> 4);
                ldsm4(a_regs[mf], sA + sw_off(row, c16));
            }
            #pragma unroll
            for (int ng = 0; ng < 2; ++ng) {
                uint32_t b_regs[4];
                int row = warp_n * 32 + ng * 16 + (lane & 7) + ((lane >> 4) << 3);
                int c16 = ks * 2 + ((lane >> 3) & 1);
                ldsm4(b_regs, bB + sw_off(row, c16));
                #pragma unroll
                for (int mf = 0; mf < 2; ++mf) {
                    mma16816(acc[mf][ng * 2],     a_regs[mf], b_regs[0], b_regs[1]);
                    mma16816(acc[mf][ng * 2 + 1], a_regs[mf], b_regs[2], b_regs[3]);
                }
            }
        }

        // epilogue: dist + top-2 update (ascending n order)
        #pragma unroll
        for (int nf = 0; nf < 4; ++nf) {
            int n = nt * NTILE + warp_n * 32 + nf * 8 + 2 * (lane & 3);
            float wn0 = wns[n], wn1 = wns[n + 1];
            #pragma unroll
            for (int mf = 0; mf < 2; ++mf) {
                float d0 = fmaf(-2.f, acc[mf][nf][0], wn0);
                float d1 = fmaf(-2.f, acc[mf][nf][1], wn1);
                float d2 = fmaf(-2.f, acc[mf][nf][2], wn0);
                float d3 = fmaf(-2.f, acc[mf][nf][3], wn1);
                ins2(d0, n,     v[mf*2],   ix[mf*2]);
                ins2(d1, n + 1, v[mf*2],   ix[mf*2]);
                ins2(d2, n,     v[mf*2+1], ix[mf*2+1]);
                ins2(d3, n + 1, v[mf*2+1], ix[mf*2+1]);
            }
        }

        __syncthreads();                 // all warps done with Bs[nt&1]
        if (nt + 2 < NTILES) {
            load_b_tile(sB[nt & 1], (nt + 2) * NTILE, tid);
            CP_WAIT(1);                  // tile nt+1 complete
        } else {
            CP_WAIT(0);
        }
        __syncthreads();
    }

    // cross-thread reduction: 16 slots per row, each slot carries top-2.
    __syncthreads();
    float4* red = reinterpret_cast<float4*>(smem);   // reuse A region: 128*16*16B = 32KB
    #pragma unroll
    for (int s = 0; s < 4; ++s) {
        int mf = s >> 1, half = s & 1;
        int row = warp_m * 32 + mf * 16 + half * 8 + (lane >> 2);
        int slot = warp_n * 4 + (lane & 3);
        red[row * 16 + slot] = make_float4(v[s][0], __int_as_float(ix[s][0]),
                                           v[s][1], __int_as_float(ix[s][1]));
    }
    __syncthreads();
    if (tid < MT) {
        float bv[3] = {3.4e38f, 3.4e38f, 3.4e38f};
        int   bi[3] = {0, 0, 0};
        #pragma unroll
        for (int s = 0; s < 16; ++s) {
            float4 e = red[tid * 16 + s];
            ins3t(e.x, __float_as_int(e.y), bv, bi);
            ins3t(e.z, __float_as_int(e.w), bv, bi);
        }
        int m = m0 + tid;
        g_argmin[m] = bi[0];
        if (bv[1] - bv[0] < MARGIN) {
            int p = atomicAdd(&g_qcount, 1);
            g_qm[p] = m; g_qa[p] = bi[0]; g_qb[p] = bi[1]; g_qc[p] = bi[2];
        }
    }
}

// ============================================================================
// Kernel 4: exact fp32 rescue among top-3 candidates (tiny queue).
// ============================================================================
__global__ void __launch_bounds__(256)
rescue_kernel(const float* __restrict__ x, const float* __restrict__ w) {
    const int gw = (blockIdx.x * blockDim.x + threadIdx.x) >> 5;
    const int lane = threadIdx.x & 31;
    const int nw = (gridDim.x * blockDim.x) >> 5;
    const int cnt = g_qcount;
    for (int i = gw; i < cnt; i += nw) {
        int m = g_qm[i], ja = g_qa[i], jb = g_qb[i], jc = g_qc[i];
        int b = m >> 12, hw = m & (HW - 1);
        const float* xp = x + (size_t)b * (DIM * HW) + hw;
        float sa = 0.f, sb2 = 0.f, sc = 0.f;
        #pragma unroll 4
        for (int c = lane; c < DIM; c += 32) {
            float xv = xp[(size_t)c * HW];
            sa  = fmaf(xv, w[(size_t)ja * DIM + c], sa);
            sb2 = fmaf(xv, w[(size_t)jb * DIM + c], sb2);
            sc  = fmaf(xv, w[(size_t)jc * DIM + c], sc);
        }
        #pragma unroll
        for (int o = 16; o > 0; o >>= 1) {
            sa  += __shfl_xor_sync(0xFFFFFFFF, sa, o);
            sb2 += __shfl_xor_sync(0xFFFFFFFF, sb2, o);
            sc  += __shfl_xor_sync(0xFFFFFFFF, sc, o);
        }
        if (lane == 0) {
            float da = fmaf(-2.0f, sa,  g_wnorm[ja]);
            float db = fmaf(-2.0f, sb2, g_wnorm[jb]);
            float dc = fmaf(-2.0f, sc,  g_wnorm[jc]);
            float wv = da; int wi = ja;
            if (better(db, jb, wv, wi)) { wv = db; wi = jb; }
            if (better(dc, jc, wv, wi)) { wv = dc; wi = jc; }
            g_argmin[m] = wi;
        }
    }
}

// ============================================================================
// Kernel 5: gather quantized output + per-block loss partials.
// ============================================================================
__global__ void __launch_bounds__(256)
gather_loss_kernel(const float* __restrict__ x, const float* __restrict__ w,
                   float* __restrict__ out) {
    __shared__ float red[256];
    const int t = threadIdx.x;
    const long base = ((long)blockIdx.x * 256 + t) * 4;

    float4 xv = *reinterpret_cast<const float4*>(x + base);
    int hw = (int)(base & (HW - 1));
    int c  = (int)((base >> 12) & (DIM - 1));
    int b  = (int)(base >> 20);
    int m  = (b << 12) | hw;

    int4 jj = *reinterpret_cast<const int4*>(g_argmin + m);
    float4 q;
    q.x = w[(size_t)jj.x * DIM + c];
    q.y = w[(size_t)jj.y * DIM + c];
    q.z = w[(size_t)jj.z * DIM + c];
    q.w = w[(size_t)jj.w * DIM + c];
    *reinterpret_cast<float4*>(out + base) = q;

    float d0 = q.x - xv.x, d1 = q.y - xv.y, d2 = q.z - xv.z, d3 = q.w - xv.w;
    red[t] = d0 * d0 + d1 * d1 + d2 * d2 + d3 * d3;
    __syncthreads();
    #pragma unroll
    for (int o = 128; o > 0; o >>= 1) {
        if (t < o) red[t] += red[t + o];
        __syncthreads();
    }
    if (t == 0) g_part[blockIdx.x] = red[0];
}

__global__ void __launch_bounds__(256)
finalize_kernel(float* __restrict__ out, int loss_idx) {
    __shared__ float red[256];
    const int t = threadIdx.x;
    float s = 0.0f;
    #pragma unroll
    for (int i = 0; i < GATHER_BLOCKS / 256; ++i)
        s += g_part[t + (i << 8)];
    red[t] = s;
    __syncthreads();
    #pragma unroll
    for (int o = 128; o > 0; o >>= 1) {
        if (t < o) red[t] += red[t + o];
        __syncthreads();
    }
    if (t == 0)
        out[loss_idx] = 0.25f * red[0] / (float)TOTAL_ELEMS;
}

// ============================================================================
extern "C" void kernel_launch(void* const* d_in, const int* in_sizes, int n_in,
                              void* d_out, int out_size) {
    const float* x = (const float*)d_in[0];   // [16,256,64,64]
    const float* w = (const float*)d_in[1];   // [2048,256]
    float* out = (float*)d_out;

    cudaFuncSetAttribute(mma_argmin_kernel,
                         cudaFuncAttributeMaxDynamicSharedMemorySize, SM_TOT);

    wnorm_kernel<<<NCODE * 32 / 256, 256>>>(w);
    wsplit_kernel<<<NCODE * DIM / 256, 256>>>(w);
    xsplit_kernel<<<dim3(HW / 32, DIM / 32, 16), 256>>>(x);
    mma_argmin_kernel<<<NVEC / MT, NTHR, SM_TOT>>>();
    rescue_kernel<<<64, 256>>>(x, w);
    gather_loss_kernel<<<GATHER_BLOCKS, 256>>>(x, w, out);
    finalize_kernel<<<1, 256>>>(out, out_size - 1);
}

// round 5
// speedup vs baseline: 5.4614x; 1.2270x over previous
#include <cuda_runtime.h>
#include <cuda_fp16.h>
#include <cstdint>
#include <climits>

// ---------------- problem constants ----------------
#define NVEC   65536
#define DIM    256
#define NCODE  2048
#define HW     4096
#define TOTAL_ELEMS 16777216

// rescue margin: keys are 256*dist quantized; 72/256 = 0.28 distance units
#define KMARGIN (72 * 2048)

// ---------------- GEMM config ----------------
#define MT 128          // M rows per CTA
#define NTILE 128       // N per tile
#define NTILES 16       // 2048 / 128
#define KSTEPS 16       // 256 / 16
#define NTHR 512        // 16 warps

// smem layout (bytes, dynamic)
#define SM_A   0
#define SM_B0  65536
#define SM_B1  131072
#define SM_WN  196608
#define SM_TOT 204800

// ---------------- device globals ----------------
__device__ int    g_argmin[NVEC];
__device__ float  g_dist[NVEC];        // best distance (wnorm - 2*dot), approx or exact
__device__ float  g_wnorm256[NCODE];   // 256 * ||w_j||^2
__device__ float  g_xnp[8][NVEC];      // xnorm partials (8 c-blocks of 32)
__device__ float  g_part[64];
__device__ __half g_xh[(size_t)NVEC * DIM];
__device__ __half g_wh[(size_t)NCODE * DIM];
__device__ int    g_qcount;
__device__ int    g_qm[NVEC], g_qa[NVEC], g_qb[NVEC], g_qc[NVEC];

// ---------------- PTX helpers ----------------
static __device__ __forceinline__ uint32_t smem_u32(const void* p) {
    uint32_t a;
    asm("{ .reg .u64 t; cvta.to.shared.u64 t, %1; cvt.u32.u64 %0, t; }" : "=r"(a) : "l"(p));
    return a;
}
#define CP_ASYNC16(dst, src) \
    asm volatile("cp.async.cg.shared.global [%0], [%1], 16;" :: "r"(dst), "l"(src))
#define CP_COMMIT() asm volatile("cp.async.commit_group;" ::: "memory")
#define CP_WAIT(n)  asm volatile("cp.async.wait_group %0;" :: "n"(n) : "memory")

static __device__ __forceinline__ void ldsm4(uint32_t* r, uint32_t addr) {
    asm volatile("ldmatrix.sync.aligned.m8n8.x4.shared.b16 {%0,%1,%2,%3}, [%4];"
        : "=r"(r[0]), "=r"(r[1]), "=r"(r[2]), "=r"(r[3]) : "r"(addr));
}
static __device__ __forceinline__ void mma16816(float* c, const uint32_t* a,
                                                uint32_t b0, uint32_t b1) {
    asm volatile("mma.sync.aligned.m16n8k16.row.col.f32.f16.f16.f32 "
        "{%0,%1,%2,%3}, {%4,%5,%6,%7}, {%8,%9}, {%0,%1,%2,%3};"
        : "+f"(c[0]), "+f"(c[1]), "+f"(c[2]), "+f"(c[3])
        : "r"(a[0]), "r"(a[1]), "r"(a[2]), "r"(a[3]), "r"(b0), "r"(b1));
}

// swizzled byte offset for (row, 16B-chunk) in a 512B-per-row tile
static __device__ __forceinline__ uint32_t sw_off(int row, int c16) {
    return (uint32_t)row * 512u + ((uint32_t)(c16 ^ (row & 7)) << 4);
}

// branchless int top-2 (key encodes dist*256 in high bits, code index in low 11)
static __device__ __forceinline__ void ktop2(int k, int* b) {
    int lo = min(b[0], k), hi = max(b[0], k);
    b[0] = lo;
    b[1] = min(b[1], hi);
}
static __device__ __forceinline__ void kins3(int k, int* b) {
    if (k < b[0])      { b[2] = b[1]; b[1] = b[0]; b[0] = k; }
    else if (k < b[1]) { b[2] = b[1]; b[1] = k; }
    else if (k < b[2]) { b[2] = k; }
}
static __device__ __forceinline__ bool better(float a, int ia, float b, int ib) {
    return (a < b) || (a == b && ia < ib);
}

// ============================================================================
// Kernel 0: codebook prep — fp16 convert + 256*||w||^2 + queue reset.
// One warp per codebook row.
// ============================================================================
__global__ void __launch_bounds__(256) wprep_kernel(const float* __restrict__ w) {
    if (blockIdx.x == 0 && threadIdx.x == 0) g_qcount = 0;
    int gwarp = (blockIdx.x * blockDim.x + threadIdx.x) >> 5;
    int lane  = threadIdx.x & 31;
    if (gwarp >= NCODE) return;
    const float4* row = reinterpret_cast<const float4*>(w + (size_t)gwarp * DIM);
    float4 v0 = row[lane];
    float4 v1 = row[lane + 32];
    __half2* dst = reinterpret_cast<__half2*>(g_wh + (size_t)gwarp * DIM);
    dst[lane * 2]      = __floats2half2_rn(v0.x, v0.y);
    dst[lane * 2 + 1]  = __floats2half2_rn(v0.z, v0.w);
    dst[64 + lane * 2]     = __floats2half2_rn(v1.x, v1.y);
    dst[64 + lane * 2 + 1] = __floats2half2_rn(v1.z, v1.w);
    float s = v0.x*v0.x + v0.y*v0.y + v0.z*v0.z + v0.w*v0.w
            + v1.x*v1.x + v1.y*v1.y + v1.z*v1.z + v1.w*v1.w;
    #pragma unroll
    for (int o = 16; o > 0; o >>= 1)
        s += __shfl_xor_sync(0xFFFFFFFF, s, o);
    if (lane == 0) g_wnorm256[gwarp] = s * 256.0f;
}

// ============================================================================
// Kernel 1: x transpose [b][c][hw] -> g_xh[m][c] fp16, plus xnorm partials.
// ============================================================================
__global__ void __launch_bounds__(256) xsplit_kernel(const float* __restrict__ x) {
    __shared__ float t[32][33];
    int bx = blockIdx.x, by = blockIdx.y, b = blockIdx.z;
    int tx = threadIdx.x & 31, ty = threadIdx.x >> 5;
    const float* xp = x + (size_t)b * (DIM * HW) + (size_t)(by * 32) * HW + bx * 32;
    #pragma unroll
    for (int i = 0; i < 4; ++i)
        t[ty + i * 8][tx] = xp[(size_t)(ty + i * 8) * HW + tx];
    __syncthreads();
    #pragma unroll
    for (int i = 0; i < 4; ++i) {
        int hwr = ty + i * 8;
        int m = b * HW + bx * 32 + hwr;
        float v = t[tx][hwr];
        g_xh[(size_t)m * DIM + by * 32 + tx] = __float2half_rn(v);
        float q = v * v;
        #pragma unroll
        for (int o = 16; o > 0; o >>= 1)
            q += __shfl_xor_sync(0xFFFFFFFF, q, o);
        if (tx == 0) g_xnp[by][m] = q;
    }
}

// ============================================================================
// Kernel 2: fp16 HMMA distance GEMM + fused top-k argmin (int-key epilogue).
// 512 threads, 16 warps: warp grid 4m x 4n, warp tile 32 rows x 32 cols.
// key = rint(256*dist)*2048 + n ; dist = ||w||^2 - 2*(x.w)
// ============================================================================
static __device__ __forceinline__ void load_b_tile(uint32_t dstbase, int n0, int tid) {
    const __half* bsrc = g_wh + (size_t)n0 * DIM;
    #pragma unroll
    for (int it = 0; it < 8; ++it) {
        int id = tid + it * NTHR;
        int row = id >> 5, c16 = id & 31;
        CP_ASYNC16(dstbase + sw_off(row, c16), bsrc + (size_t)row * DIM + c16 * 8);
    }
    CP_COMMIT();
}

__global__ void __launch_bounds__(NTHR, 1) mma_argmin_kernel() {
    extern __shared__ char smem[];
    const uint32_t sb = smem_u32(smem);
    const uint32_t sA = sb + SM_A;
    const uint32_t sB[2] = { sb + SM_B0, sb + SM_B1 };
    float* wns = reinterpret_cast<float*>(smem + SM_WN);   // 256*wnorm

    const int tid = threadIdx.x;
    const int lane = tid & 31, wid = tid >> 5;
    const int warp_m = wid & 3;      // 4 m-quadrants of 32 rows
    const int warp_n = wid >> 2;     // 4 n-quarters of 32 cols
    const int m0 = blockIdx.x * MT;

    // pre-scaled wnorm -> smem
    #pragma unroll
    for (int i = tid; i < NCODE; i += NTHR) wns[i] = g_wnorm256[i];

    // A tile (128 x 256 fp16 = 64KB) via cp.async
    {
        const __half* asrc = g_xh + (size_t)m0 * DIM;
        #pragma unroll
        for (int it = 0; it < 8; ++it) {
            int id = tid + it * NTHR;
            int row = id >> 5, c16 = id & 31;
            CP_ASYNC16(sA + sw_off(row, c16), asrc + (size_t)row * DIM + c16 * 8);
        }
        CP_COMMIT();
    }
    load_b_tile(sB[0], 0, tid);
    load_b_tile(sB[1], NTILE, tid);
    CP_WAIT(1);              // A + B0 ready
    __syncthreads();

    // per-thread top-2 int keys for 4 row-slots (slot = mf*2 + half)
    int kk[4][2];
    #pragma unroll
    for (int s = 0; s < 4; ++s) { kk[s][0] = INT_MAX; kk[s][1] = INT_MAX; }

    #pragma unroll 1
    for (int nt = 0; nt < NTILES; ++nt) {
        const uint32_t bB = sB[nt & 1];
        float acc[2][4][4];
        #pragma unroll
        for (int mf = 0; mf < 2; ++mf)
            #pragma unroll
            for (int nf = 0; nf < 4; ++nf)
                #pragma unroll
                for (int c = 0; c < 4; ++c) acc[mf][nf][c] = 0.f;

        #pragma unroll
        for (int ks = 0; ks < KSTEPS; ++ks) {
            uint32_t a_regs[2][4];
            #pragma unroll
            for (int mf = 0; mf < 2; ++mf) {
                int row = warp_m * 32 + mf * 16 + (lane & 15);
                int c16 = ks * 2 + (lane >> 4);
                ldsm4(a_regs[mf], sA + sw_off(row, c16));
            }
            #pragma unroll
            for (int ng = 0; ng < 2; ++ng) {
                uint32_t b_regs[4];
                int row = warp_n * 32 + ng * 16 + (lane & 7) + ((lane >> 4) << 3);
                int c16 = ks * 2 + ((lane >> 3) & 1);
                ldsm4(b_regs, bB + sw_off(row, c16));
                #pragma unroll
                for (int mf = 0; mf < 2; ++mf) {
                    mma16816(acc[mf][ng * 2],     a_regs[mf], b_regs[0], b_regs[1]);
                    mma16816(acc[mf][ng * 2 + 1], a_regs[mf], b_regs[2], b_regs[3]);
                }
            }
        }

        // epilogue: int-key distance + branchless top-2
        #pragma unroll
        for (int nf = 0; nf < 4; ++nf) {
            int n = nt * NTILE + warp_n * 32 + nf * 8 + 2 * (lane & 3);
            float wn0 = wns[n], wn1 = wns[n + 1];
            #pragma unroll
            for (int mf = 0; mf < 2; ++mf) {
                int k0 = __float2int_rn(fmaf(-512.f, acc[mf][nf][0], wn0)) * 2048 + n;
                int k1 = __float2int_rn(fmaf(-512.f, acc[mf][nf][1], wn1)) * 2048 + (n + 1);
                int k2 = __float2int_rn(fmaf(-512.f, acc[mf][nf][2], wn0)) * 2048 + n;
                int k3 = __float2int_rn(fmaf(-512.f, acc[mf][nf][3], wn1)) * 2048 + (n + 1);
                ktop2(k0, kk[mf * 2]);
                ktop2(k1, kk[mf * 2]);
                ktop2(k2, kk[mf * 2 + 1]);
                ktop2(k3, kk[mf * 2 + 1]);
            }
        }

        __syncthreads();                 // all warps done with Bs[nt&1]
        if (nt + 2 < NTILES) {
            load_b_tile(sB[nt & 1], (nt + 2) * NTILE, tid);
            CP_WAIT(1);                  // tile nt+1 complete
        } else {
            CP_WAIT(0);
        }
        __syncthreads();
    }

    // cross-thread reduction: 16 slots per row, each slot carries top-2 keys
    __syncthreads();
    int2* red = reinterpret_cast<int2*>(smem);   // reuse A region: 128*16*8B = 16KB
    #pragma unroll
    for (int s = 0; s < 4; ++s) {
        int mf = s >> 1, half = s & 1;
        int row = warp_m * 32 + mf * 16 + half * 8 + (lane >> 2);
        int slot = warp_n * 4 + (lane & 3);
        red[row * 16 + slot] = make_int2(kk[s][0], kk[s][1]);
    }
    __syncthreads();
    if (tid < MT) {
        int b[3] = { INT_MAX, INT_MAX, INT_MAX };
        #pragma unroll
        for (int s = 0; s < 16; ++s) {
            int2 e = red[tid * 16 + s];
            kins3(e.x, b);
            kins3(e.y, b);
        }
        int m = m0 + tid;
        g_argmin[m] = b[0] & 2047;
        g_dist[m] = (float)(b[0] >> 11) * (1.0f / 256.0f);
        if (b[1] - b[0] < KMARGIN) {
            int p = atomicAdd(&g_qcount, 1);
            g_qm[p] = m; g_qa[p] = b[0] & 2047; g_qb[p] = b[1] & 2047; g_qc[p] = b[2] & 2047;
        }
    }
}

// ============================================================================
// Kernel 3: exact fp32 rescue among top-3 candidates (small queue).
// Also writes exact distance for the loss.
// ============================================================================
__global__ void __launch_bounds__(256)
rescue_kernel(const float* __restrict__ x, const float* __restrict__ w) {
    const int gw = (blockIdx.x * blockDim.x + threadIdx.x) >> 5;
    const int lane = threadIdx.x & 31;
    const int nw = (gridDim.x * blockDim.x) >> 5;
    const int cnt = g_qcount;
    for (int i = gw; i < cnt; i += nw) {
        int m = g_qm[i], ja = g_qa[i], jb = g_qb[i], jc = g_qc[i];
        int b = m >> 12, hw = m & (HW - 1);
        const float* xp = x + (size_t)b * (DIM * HW) + hw;
        float sa = 0.f, sb2 = 0.f, sc = 0.f;
        #pragma unroll 4
        for (int c = lane; c < DIM; c += 32) {
            float xv = xp[(size_t)c * HW];
            sa  = fmaf(xv, w[(size_t)ja * DIM + c], sa);
            sb2 = fmaf(xv, w[(size_t)jb * DIM + c], sb2);
            sc  = fmaf(xv, w[(size_t)jc * DIM + c], sc);
        }
        #pragma unroll
        for (int o = 16; o > 0; o >>= 1) {
            sa  += __shfl_xor_sync(0xFFFFFFFF, sa, o);
            sb2 += __shfl_xor_sync(0xFFFFFFFF, sb2, o);
            sc  += __shfl_xor_sync(0xFFFFFFFF, sc, o);
        }
        if (lane == 0) {
            float da = fmaf(-2.0f, sa,  g_wnorm256[ja] * (1.0f / 256.0f));
            float db = fmaf(-2.0f, sb2, g_wnorm256[jb] * (1.0f / 256.0f));
            float dc = fmaf(-2.0f, sc,  g_wnorm256[jc] * (1.0f / 256.0f));
            float wv = da; int wi = ja;
            if (better(db, jb, wv, wi)) { wv = db; wi = jb; }
            if (better(dc, jc, wv, wi)) { wv = dc; wi = jc; }
            g_argmin[m] = wi;
            g_dist[m] = wv;
        }
    }
}

// ============================================================================
// Kernel 4: pure gather — out[b][c][hw] = w[argmin[m]][c]. No x read.
// ============================================================================
__global__ void __launch_bounds__(256)
gather_kernel(const float* __restrict__ w, float* __restrict__ out) {
    const long base = ((long)blockIdx.x * 256 + threadIdx.x) * 4;
    int hw = (int)(base & (HW - 1));
    int c  = (int)((base >> 12) & (DIM - 1));
    int b  = (int)(base >> 20);
    int m  = (b << 12) | hw;

    int4 jj = *reinterpret_cast<const int4*>(g_argmin + m);
    float4 q;
    q.x = w[(size_t)jj.x * DIM + c];
    q.y = w[(size_t)jj.y * DIM + c];
    q.z = w[(size_t)jj.z * DIM + c];
    q.w = w[(size_t)jj.w * DIM + c];
    *reinterpret_cast<float4*>(out + base) = q;
}

// ============================================================================
// Kernel 5/6: loss = 0.25 * sum_m(dist[m] + xnorm[m]) / TOTAL_ELEMS
// Deterministic fixed-order two-stage reduction.
// ============================================================================
__global__ void __launch_bounds__(256)
losspart_kernel() {
    __shared__ float red[256];
    const int t = threadIdx.x;
    const int gt = blockIdx.x * 256 + t;     // 16384 threads
    float s = 0.f;
    #pragma unroll
    for (int r = 0; r < 4; ++r) {
        int m = gt + r * 16384;
        float xn = g_dist[m];
        #pragma unroll
        for (int by = 0; by < 8; ++by) xn += g_xnp[by][m];
        s += xn;
    }
    red[t] = s;
    __syncthreads();
    #pragma unroll
    for (int o = 128; o > 0; o >>= 1) {
        if (t < o) red[t] += red[t + o];
        __syncthreads();
    }
    if (t == 0) g_part[blockIdx.x] = red[0];
}

__global__ void __launch_bounds__(64)
finalize_kernel(float* __restrict__ out, int loss_idx) {
    __shared__ float red[64];
    const int t = threadIdx.x;
    red[t] = g_part[t];
    __syncthreads();
    #pragma unroll
    for (int o = 32; o > 0; o >>= 1) {
        if (t < o) red[t] += red[t + o];
        __syncthreads();
    }
    if (t == 0)
        out[loss_idx] = 0.25f * red[0] / (float)TOTAL_ELEMS;
}

// ============================================================================
extern "C" void kernel_launch(void* const* d_in, const int* in_sizes, int n_in,
                              void* d_out, int out_size) {
    const float* x = (const float*)d_in[0];   // [16,256,64,64]
    const float* w = (const float*)d_in[1];   // [2048,256]
    float* out = (float*)d_out;

    cudaFuncSetAttribute(mma_argmin_kernel,
                         cudaFuncAttributeMaxDynamicSharedMemorySize, SM_TOT);

    wprep_kernel<<<NCODE * 32 / 256, 256>>>(w);
    xsplit_kernel<<<dim3(HW / 32, DIM / 32, 16), 256>>>(x);
    mma_argmin_kernel<<<NVEC / MT, NTHR, SM_TOT>>>();
    rescue_kernel<<<64, 256>>>(x, w);
    gather_kernel<<<TOTAL_ELEMS / 1024, 256>>>(w, out);
    losspart_kernel<<<64, 256>>>();
    finalize_kernel<<<1, 64>>>(out, out_size - 1);
}